// round 15
// baseline (speedup 1.0000x reference)
#include <cuda_runtime.h>
#include <cuda_bf16.h>
#include <math.h>
#include <stdint.h>

// Problem constants
#define B_ 4
#define S_ 2048
#define H_ 16
#define D_ 64
#define DM_ 1024
#define M8_ 8192
#define BH_ 64
#define SCALE_ 0.125f
#define EPS_ 1e-6f

#define OUT_ELEMS   (M8_ * DM_)
#define ATTN_ELEMS  ((size_t)BH_ * S_ * S_)

// ---------------- device scratch -----------------------------------------------
// QH/KH/VH hold tf32-ROUNDED values in FRAGMENT-MAJOR tile layouts (see R13).
// QHf additionally pre-scaled by 1/8.
__device__ float g_QH[(size_t)BH_ * S_ * D_];
__device__ float g_KH[(size_t)BH_ * S_ * D_];
__device__ float g_VH[(size_t)BH_ * S_ * D_];
__device__ float g_AO[(size_t)M8_ * DM_];       // [B,S,H*D] fp32
__device__ float g_FC[(size_t)M8_ * DM_];
__device__ float g_M[(size_t)BH_ * S_];
__device__ float g_L[(size_t)BH_ * S_];

// ---------------- tf32 helpers ---------------------------------------------------
__device__ __forceinline__ uint32_t f2tf32(float x) {
    uint32_t u;
    asm("cvt.rna.tf32.f32 %0, %1;" : "=r"(u) : "f"(x));
    return u;
}

__device__ __forceinline__ void mma8(float* c, const uint32_t* a, const uint32_t* b) {
    asm volatile(
        "mma.sync.aligned.m16n8k8.row.col.f32.tf32.tf32.f32 "
        "{%0,%1,%2,%3}, {%4,%5,%6,%7}, {%8,%9}, {%0,%1,%2,%3};"
        : "+f"(c[0]), "+f"(c[1]), "+f"(c[2]), "+f"(c[3])
        : "r"(a[0]), "r"(a[1]), "r"(a[2]), "r"(a[3]), "r"(b[0]), "r"(b[1]));
}

__device__ __forceinline__ void cp16(uint32_t saddr, const void* g) {
    asm volatile("cp.async.cg.shared.global [%0], [%1], 16;" :: "r"(saddr), "l"(g));
}
__device__ __forceinline__ void cp_commit() {
    asm volatile("cp.async.commit_group;");
}

// =================================================================================
// tf32 GEMM (unchanged from R13): hm 0=row-major fc; 1=Q-frag; 2=K-frag; 3=V-frag.
// =================================================================================
#define GEMM_SMEM_BYTES (4 * 128 * 36 * 4)

__global__ __launch_bounds__(256) void gemm_tf32_kernel(
    const float* __restrict__ A, const float* __restrict__ W, float* __restrict__ C,
    int K, int hm, const float* __restrict__ resid, float oscale) {
    extern __shared__ uint32_t dynsm[];
    uint32_t* As = dynsm;
    uint32_t* Ws = dynsm + 2 * 4608;

    const int tid = threadIdx.x;
    const int lane = tid & 31, warp = tid >> 5;
    const int wm = warp >> 1, wn = warp & 1;
    const int rm = wm * 32, cn = wn * 64;
    const int m0 = blockIdx.y * 128, n0 = blockIdx.x * 128;

    const int lr0 = tid >> 3, lr1 = (tid + 256) >> 3, lr2 = (tid + 512) >> 3, lr3 = (tid + 768) >> 3;
    const int lc = (tid & 7) * 4;

    float acc[2][8][4];
#pragma unroll
    for (int mt = 0; mt < 2; mt++)
#pragma unroll
        for (int nt = 0; nt < 8; nt++)
#pragma unroll
            for (int i = 0; i < 4; i++) acc[mt][nt][i] = 0.f;

    const int NT = K >> 5;

    float4 pa0, pa1, pa2, pa3, pw0, pw1, pw2, pw3;
    pa0 = *(const float4*)(A + (size_t)(m0 + lr0) * K + lc);
    pa1 = *(const float4*)(A + (size_t)(m0 + lr1) * K + lc);
    pa2 = *(const float4*)(A + (size_t)(m0 + lr2) * K + lc);
    pa3 = *(const float4*)(A + (size_t)(m0 + lr3) * K + lc);
    pw0 = *(const float4*)(W + (size_t)(n0 + lr0) * K + lc);
    pw1 = *(const float4*)(W + (size_t)(n0 + lr1) * K + lc);
    pw2 = *(const float4*)(W + (size_t)(n0 + lr2) * K + lc);
    pw3 = *(const float4*)(W + (size_t)(n0 + lr3) * K + lc);

#define STORE_TILE(buf)                                                                    \
    do {                                                                                   \
        uint32_t* Ab_ = As + (buf) * 4608;                                                 \
        uint32_t* Wb_ = Ws + (buf) * 4608;                                                 \
        *(uint4*)&Ab_[lr0 * 36 + lc] = make_uint4(f2tf32(pa0.x), f2tf32(pa0.y), f2tf32(pa0.z), f2tf32(pa0.w)); \
        *(uint4*)&Ab_[lr1 * 36 + lc] = make_uint4(f2tf32(pa1.x), f2tf32(pa1.y), f2tf32(pa1.z), f2tf32(pa1.w)); \
        *(uint4*)&Ab_[lr2 * 36 + lc] = make_uint4(f2tf32(pa2.x), f2tf32(pa2.y), f2tf32(pa2.z), f2tf32(pa2.w)); \
        *(uint4*)&Ab_[lr3 * 36 + lc] = make_uint4(f2tf32(pa3.x), f2tf32(pa3.y), f2tf32(pa3.z), f2tf32(pa3.w)); \
        *(uint4*)&Wb_[lr0 * 36 + lc] = make_uint4(f2tf32(pw0.x), f2tf32(pw0.y), f2tf32(pw0.z), f2tf32(pw0.w)); \
        *(uint4*)&Wb_[lr1 * 36 + lc] = make_uint4(f2tf32(pw1.x), f2tf32(pw1.y), f2tf32(pw1.z), f2tf32(pw1.w)); \
        *(uint4*)&Wb_[lr2 * 36 + lc] = make_uint4(f2tf32(pw2.x), f2tf32(pw2.y), f2tf32(pw2.z), f2tf32(pw2.w)); \
        *(uint4*)&Wb_[lr3 * 36 + lc] = make_uint4(f2tf32(pw3.x), f2tf32(pw3.y), f2tf32(pw3.z), f2tf32(pw3.w)); \
    } while (0)

    STORE_TILE(0);

    for (int kt = 0; kt < NT; kt++) {
        __syncthreads();
        if (kt + 1 < NT) {
            const int ko = (kt + 1) * 32;
            pa0 = *(const float4*)(A + (size_t)(m0 + lr0) * K + ko + lc);
            pa1 = *(const float4*)(A + (size_t)(m0 + lr1) * K + ko + lc);
            pa2 = *(const float4*)(A + (size_t)(m0 + lr2) * K + ko + lc);
            pa3 = *(const float4*)(A + (size_t)(m0 + lr3) * K + ko + lc);
            pw0 = *(const float4*)(W + (size_t)(n0 + lr0) * K + ko + lc);
            pw1 = *(const float4*)(W + (size_t)(n0 + lr1) * K + ko + lc);
            pw2 = *(const float4*)(W + (size_t)(n0 + lr2) * K + ko + lc);
            pw3 = *(const float4*)(W + (size_t)(n0 + lr3) * K + ko + lc);
        }

        const uint32_t* Ab = As + (kt & 1) * 4608;
        const uint32_t* Wb = Ws + (kt & 1) * 4608;
#pragma unroll
        for (int kk = 0; kk < 4; kk++) {
            const int c0 = kk * 8 + (lane & 3);
            uint32_t a[2][4];
#pragma unroll
            for (int mt = 0; mt < 2; mt++) {
                int r0 = rm + mt * 16 + (lane >> 2);
                a[mt][0] = Ab[r0 * 36 + c0];
                a[mt][1] = Ab[(r0 + 8) * 36 + c0];
                a[mt][2] = Ab[r0 * 36 + c0 + 4];
                a[mt][3] = Ab[(r0 + 8) * 36 + c0 + 4];
            }
            uint32_t b[8][2];
#pragma unroll
            for (int nt = 0; nt < 8; nt++) {
                int rb = cn + nt * 8 + (lane >> 2);
                b[nt][0] = Wb[rb * 36 + c0];
                b[nt][1] = Wb[rb * 36 + c0 + 4];
            }
#pragma unroll
            for (int mt = 0; mt < 2; mt++)
#pragma unroll
                for (int nt = 0; nt < 8; nt++) mma8(acc[mt][nt], a[mt], b[nt]);
        }

        if (kt + 1 < NT) STORE_TILE((kt + 1) & 1);
    }

#pragma unroll
    for (int mt = 0; mt < 2; mt++) {
#pragma unroll
        for (int nt = 0; nt < 8; nt++) {
#pragma unroll
            for (int half = 0; half < 2; half++) {
                int row = m0 + rm + mt * 16 + (lane >> 2) + half * 8;
                int col = n0 + cn + nt * 8 + 2 * (lane & 3);
                float v0 = acc[mt][nt][half * 2 + 0];
                float v1 = acc[mt][nt][half * 2 + 1];
                if (resid) {
                    v0 += resid[(size_t)row * DM_ + col];
                    v1 += resid[(size_t)row * DM_ + col + 1];
                }
                if (hm == 0) {
                    *(float2*)&C[(size_t)row * DM_ + col] = make_float2(v0, v1);
                } else {
                    v0 = __uint_as_float(f2tf32(v0 * oscale));
                    v1 = __uint_as_float(f2tf32(v1 * oscale));
                    int b = row >> 11, s = row & (S_ - 1);
                    int h = col >> 6, d = col & (D_ - 1);
                    int bh = b * H_ + h;
                    if (hm == 1) {
                        int qt = s >> 7, r = s & 127, rg = r >> 4, rr = r & 15;
                        int g8 = rr & 7, hi = rr >> 3;
                        size_t base = ((size_t)bh * 16 + qt) * 8192;
                        int kk = d >> 3, cc = d & 7, t = cc & 3, w = cc >> 2;
                        C[base + (size_t)(((rg * 8 + kk) * 32 + (g8 * 4 + t)) * 4 + hi + 2 * w)] = v0;
                        int d1 = d + 1; kk = d1 >> 3; cc = d1 & 7; t = cc & 3; w = cc >> 2;
                        C[base + (size_t)(((rg * 8 + kk) * 32 + (g8 * 4 + t)) * 4 + hi + 2 * w)] = v1;
                    } else if (hm == 2) {
                        int kt = s >> 6, r = s & 63, nt2 = r >> 3, g8 = r & 7;
                        size_t base = ((size_t)bh * 32 + kt) * 4096;
                        int kk = d >> 3, cc = d & 7, t = cc & 3, w = cc >> 2;
                        C[base + (size_t)(((kk * 8 + nt2) * 32 + (g8 * 4 + t)) * 2 + w)] = v0;
                        int d1 = d + 1; kk = d1 >> 3; cc = d1 & 7; t = cc & 3; w = cc >> 2;
                        C[base + (size_t)(((kk * 8 + nt2) * 32 + (g8 * 4 + t)) * 2 + w)] = v1;
                    } else {
                        int kt = s >> 6, rk = s & 63, kc = rk >> 3, u = rk & 7;
                        int t = u & 3, w = u >> 2;
                        size_t base = ((size_t)bh * 32 + kt) * 4096;
                        int nt2 = d >> 3, g8 = d & 7;
                        C[base + (size_t)(((kc * 8 + nt2) * 32 + (g8 * 4 + t)) * 2 + w)] = v0;
                        int d1 = d + 1; nt2 = d1 >> 3; g8 = d1 & 7;
                        C[base + (size_t)(((kc * 8 + nt2) * 32 + (g8 * 4 + t)) * 2 + w)] = v1;
                    }
                }
            }
        }
    }
#undef STORE_TILE
}

// =================================================================================
// Pass 1 (stats): QK^T + online max/sum only -> Mv, Lv. No V, no PV.
// smem: Qf[8192] + K stages 8192+st*4096 = 16384 words (64 KB) -> 3 CTAs/SM.
// =================================================================================
#define ST_SMEM_BYTES (16384 * 4)

__global__ __launch_bounds__(256, 3) void attn_stats_kernel(
    const float* __restrict__ QHf, const float* __restrict__ KHf,
    float* __restrict__ Mv, float* __restrict__ Lv) {
    extern __shared__ uint32_t sm[];
    const uint32_t sbase = (uint32_t)__cvta_generic_to_shared(sm);

    const int tid = threadIdx.x;
    const int lane = tid & 31, warp = tid >> 5;
    const int g = lane >> 2, t = lane & 3;
    const int r0 = warp * 16 + g;
    const int bh = blockIdx.y;
    const int q0 = blockIdx.x * 128;

    const float* Qt = QHf + ((size_t)bh * 16 + blockIdx.x) * 8192;
    const float* Kt = KHf + (size_t)bh * 32 * 4096;

    const int NT = S_ / 64;

#define ISSUE_K1(stage, kt_)                                                          \
    do {                                                                              \
        const float* Kg_ = Kt + (size_t)(kt_) * 4096;                                 \
        _Pragma("unroll")                                                             \
        for (int p = 0; p < 4; p++) {                                                 \
            int w4 = (tid + p * 256) * 4;                                             \
            cp16(sbase + (uint32_t)(8192 + (stage) * 4096 + w4) * 4, Kg_ + w4);       \
        }                                                                             \
        cp_commit();                                                                  \
    } while (0)

    // G0: Q + K0 ; G1: K1
#pragma unroll
    for (int p = 0; p < 8; p++) {
        int w4 = (tid + p * 256) * 4;
        cp16(sbase + (uint32_t)w4 * 4, Qt + w4);
    }
#pragma unroll
    for (int p = 0; p < 4; p++) {
        int w4 = (tid + p * 256) * 4;
        cp16(sbase + (uint32_t)(8192 + w4) * 4, Kt + w4);
    }
    cp_commit();
    ISSUE_K1(1, 1);

    float rowm0 = -1e30f, rowm1 = -1e30f;
    float rowl0 = 0.f, rowl1 = 0.f;

    for (int kt = 0; kt < NT; kt++) {
        if (kt + 1 < NT) asm volatile("cp.async.wait_group 1;");
        else             asm volatile("cp.async.wait_group 0;");
        __syncthreads();

        const uint32_t* Kb = sm + 8192 + (kt & 1) * 4096;

        float sacc[8][4];
#pragma unroll
        for (int nt = 0; nt < 8; nt++)
#pragma unroll
            for (int i = 0; i < 4; i++) sacc[nt][i] = 0.f;

#pragma unroll
        for (int kk = 0; kk < 8; kk++) {
            uint4 av = *(const uint4*)&sm[(((warp << 3) + kk) * 32 + lane) * 4];
            uint32_t a[4] = {av.x, av.y, av.z, av.w};
#pragma unroll
            for (int nt = 0; nt < 8; nt++) {
                uint2 bv = *(const uint2*)&Kb[((kk * 8 + nt) * 32 + lane) * 2];
                uint32_t b[2] = {bv.x, bv.y};
                mma8(sacc[nt], a, b);
            }
        }

        // online stats (identical chain to R13's attn_a -> identical Mv/Lv bits)
        float mx0 = -1e30f, mx1 = -1e30f;
#pragma unroll
        for (int nt = 0; nt < 8; nt++) {
            mx0 = fmaxf(mx0, fmaxf(sacc[nt][0], sacc[nt][1]));
            mx1 = fmaxf(mx1, fmaxf(sacc[nt][2], sacc[nt][3]));
        }
        mx0 = fmaxf(mx0, __shfl_xor_sync(0xffffffffu, mx0, 1));
        mx0 = fmaxf(mx0, __shfl_xor_sync(0xffffffffu, mx0, 2));
        mx1 = fmaxf(mx1, __shfl_xor_sync(0xffffffffu, mx1, 1));
        mx1 = fmaxf(mx1, __shfl_xor_sync(0xffffffffu, mx1, 2));

        float mn0 = fmaxf(rowm0, mx0), mn1 = fmaxf(rowm1, mx1);
        float cr0 = __expf(rowm0 - mn0), cr1 = __expf(rowm1 - mn1);
        float ps0 = 0.f, ps1 = 0.f;
#pragma unroll
        for (int nt = 0; nt < 8; nt++) {
            ps0 += __expf(sacc[nt][0] - mn0);
            ps0 += __expf(sacc[nt][1] - mn0);
            ps1 += __expf(sacc[nt][2] - mn1);
            ps1 += __expf(sacc[nt][3] - mn1);
        }
        ps0 += __shfl_xor_sync(0xffffffffu, ps0, 1);
        ps0 += __shfl_xor_sync(0xffffffffu, ps0, 2);
        ps1 += __shfl_xor_sync(0xffffffffu, ps1, 1);
        ps1 += __shfl_xor_sync(0xffffffffu, ps1, 2);
        rowl0 = rowl0 * cr0 + ps0; rowm0 = mn0;
        rowl1 = rowl1 * cr1 + ps1; rowm1 = mn1;

        __syncthreads();
        if (kt + 2 < NT) ISSUE_K1(kt & 1, kt + 2);
    }
#undef ISSUE_K1

    if (t == 0) {
        size_t mb = (size_t)bh * S_ + q0 + r0;
        Mv[mb] = rowm0;     Lv[mb] = rowl0;
        Mv[mb + 8] = rowm1; Lv[mb + 8] = rowl1;
    }
}

// =================================================================================
// Pass 2 (fused PV + attn write): m, 1/l known up-front -> P = exp(s-m)*il
// directly; NO online corrections; PV accumulates normalized P; P stored to attn.
// smem: Qf[8192] | K stages 8192+st*4096 | V stages 16384+st*4096 = 24576 words
// =================================================================================
#define PV_SMEM_BYTES (24576 * 4)

__global__ __launch_bounds__(256, 2) void attn_pv_kernel(
    const float* __restrict__ QHf, const float* __restrict__ KHf,
    const float* __restrict__ VHf, const float* __restrict__ Mv,
    const float* __restrict__ Lv, float* __restrict__ AO,
    float* __restrict__ attn) {
    extern __shared__ uint32_t sm[];
    const uint32_t sbase = (uint32_t)__cvta_generic_to_shared(sm);

    const int tid = threadIdx.x;
    const int lane = tid & 31, warp = tid >> 5;
    const int g = lane >> 2, t = lane & 3;
    const int r0 = warp * 16 + g;
    const int bh = blockIdx.y;
    const int q0 = blockIdx.x * 128;
    const int srcA = (lane & ~3) | (t >> 1);
    const int srcB = srcA + 2;

    const float* Qt = QHf + ((size_t)bh * 16 + blockIdx.x) * 8192;
    const float* Kt = KHf + (size_t)bh * 32 * 4096;
    const float* Vt = VHf + (size_t)bh * 32 * 4096;

    const int NT = S_ / 64;

#define ISSUE_KV(stage, kt_)                                                          \
    do {                                                                              \
        const float* Kg_ = Kt + (size_t)(kt_) * 4096;                                 \
        const float* Vg_ = Vt + (size_t)(kt_) * 4096;                                 \
        _Pragma("unroll")                                                             \
        for (int p = 0; p < 4; p++) {                                                 \
            int w4 = (tid + p * 256) * 4;                                             \
            cp16(sbase + (uint32_t)(8192 + (stage) * 4096 + w4) * 4, Kg_ + w4);       \
            cp16(sbase + (uint32_t)(16384 + (stage) * 4096 + w4) * 4, Vg_ + w4);      \
        }                                                                             \
        cp_commit();                                                                  \
    } while (0)

#pragma unroll
    for (int p = 0; p < 8; p++) {
        int w4 = (tid + p * 256) * 4;
        cp16(sbase + (uint32_t)w4 * 4, Qt + w4);
    }
#pragma unroll
    for (int p = 0; p < 4; p++) {
        int w4 = (tid + p * 256) * 4;
        cp16(sbase + (uint32_t)(8192 + w4) * 4, Kt + w4);
        cp16(sbase + (uint32_t)(16384 + w4) * 4, Vt + w4);
    }
    cp_commit();
    ISSUE_KV(1, 1);

    // per-lane row stats
    const size_t mb = (size_t)bh * S_ + q0 + r0;
    const float m0 = Mv[mb],     il0 = 1.f / Lv[mb];
    const float m1 = Mv[mb + 8], il1 = 1.f / Lv[mb + 8];

    float o[8][4];
#pragma unroll
    for (int nt = 0; nt < 8; nt++)
#pragma unroll
        for (int i = 0; i < 4; i++) o[nt][i] = 0.f;

    // attn row bases for this lane
    float* arow0 = attn + ((size_t)bh * S_ + (q0 + r0)) * S_;
    float* arow1 = arow0 + (size_t)8 * S_;

    for (int kt = 0; kt < NT; kt++) {
        if (kt + 1 < NT) asm volatile("cp.async.wait_group 1;");
        else             asm volatile("cp.async.wait_group 0;");
        __syncthreads();

        const uint32_t* Kb = sm + 8192 + (kt & 1) * 4096;
        const uint32_t* Vb = sm + 16384 + (kt & 1) * 4096;

        // ---- S = Qf @ K^T ---------------------------------------------------------
        float sacc[8][4];
#pragma unroll
        for (int nt = 0; nt < 8; nt++)
#pragma unroll
            for (int i = 0; i < 4; i++) sacc[nt][i] = 0.f;

#pragma unroll
        for (int kk = 0; kk < 8; kk++) {
            uint4 av = *(const uint4*)&sm[(((warp << 3) + kk) * 32 + lane) * 4];
            uint32_t a[4] = {av.x, av.y, av.z, av.w};
#pragma unroll
            for (int nt = 0; nt < 8; nt++) {
                uint2 bv = *(const uint2*)&Kb[((kk * 8 + nt) * 32 + lane) * 2];
                uint32_t b[2] = {bv.x, bv.y};
                mma8(sacc[nt], a, b);
            }
        }

        // ---- P = exp(s-m)*il (normalized), store to attn --------------------------
        const int c0 = kt * 64 + 2 * t;
#pragma unroll
        for (int nt = 0; nt < 8; nt++) {
            sacc[nt][0] = __expf(sacc[nt][0] - m0) * il0;
            sacc[nt][1] = __expf(sacc[nt][1] - m0) * il0;
            sacc[nt][2] = __expf(sacc[nt][2] - m1) * il1;
            sacc[nt][3] = __expf(sacc[nt][3] - m1) * il1;
            *(float2*)&arow0[c0 + nt * 8] = make_float2(sacc[nt][0], sacc[nt][1]);
            *(float2*)&arow1[c0 + nt * 8] = make_float2(sacc[nt][2], sacc[nt][3]);
        }

        // ---- O += P @ V (normalized P; no correction, no final divide) ------------
#pragma unroll
        for (int kc = 0; kc < 8; kc++) {
            uint32_t p0 = f2tf32(sacc[kc][0]);
            uint32_t p1 = f2tf32(sacc[kc][1]);
            uint32_t p2 = f2tf32(sacc[kc][2]);
            uint32_t p3 = f2tf32(sacc[kc][3]);
            uint32_t pa[4];
            {
                uint32_t u0 = __shfl_sync(0xffffffffu, p0, srcA);
                uint32_t u1 = __shfl_sync(0xffffffffu, p1, srcA);
                pa[0] = (lane & 1) ? u1 : u0;
                u0 = __shfl_sync(0xffffffffu, p2, srcA);
                u1 = __shfl_sync(0xffffffffu, p3, srcA);
                pa[1] = (lane & 1) ? u1 : u0;
                u0 = __shfl_sync(0xffffffffu, p0, srcB);
                u1 = __shfl_sync(0xffffffffu, p1, srcB);
                pa[2] = (lane & 1) ? u1 : u0;
                u0 = __shfl_sync(0xffffffffu, p2, srcB);
                u1 = __shfl_sync(0xffffffffu, p3, srcB);
                pa[3] = (lane & 1) ? u1 : u0;
            }
#pragma unroll
            for (int nt = 0; nt < 8; nt++) {
                uint2 bv = *(const uint2*)&Vb[((kc * 8 + nt) * 32 + lane) * 2];
                uint32_t b[2] = {bv.x, bv.y};
                mma8(o[nt], pa, b);
            }
        }

        __syncthreads();
        if (kt + 2 < NT) ISSUE_KV(kt & 1, kt + 2);
    }
#undef ISSUE_KV

    // ---- epilogue: AO = o (already normalized) -------------------------------------
    const int bb = bh >> 4, hh = bh & 15;
#pragma unroll
    for (int nt = 0; nt < 8; nt++) {
        int col = hh * D_ + nt * 8 + 2 * t;
        size_t base0 = ((size_t)bb * S_ + (q0 + r0)) * DM_ + col;
        size_t base1 = ((size_t)bb * S_ + (q0 + r0 + 8)) * DM_ + col;
        *(float2*)&AO[base0] = make_float2(o[nt][0], o[nt][1]);
        *(float2*)&AO[base1] = make_float2(o[nt][2], o[nt][3]);
    }
}

// =================================================================================
// LayerNorm over last dim (1024).
// =================================================================================
__global__ void ln_kernel(const float* __restrict__ FC, const float* __restrict__ gamma,
                          const float* __restrict__ beta, float* __restrict__ out) {
    __shared__ float sbuf[32];
    const int row = blockIdx.x;
    const int tid = threadIdx.x;
    const float* x = FC + (size_t)row * DM_;

    float v[4];
    float s = 0.f;
#pragma unroll
    for (int i = 0; i < 4; i++) { v[i] = x[tid + i * 256]; s += v[i]; }
    {
        int lane = tid & 31, wid = tid >> 5;
        for (int o = 16; o > 0; o >>= 1) s += __shfl_down_sync(0xffffffffu, s, o);
        if (lane == 0) sbuf[wid] = s;
        __syncthreads();
        if (wid == 0) {
            float tt = (lane < 8) ? sbuf[lane] : 0.f;
            for (int o = 4; o > 0; o >>= 1) tt += __shfl_down_sync(0xffffffffu, tt, o);
            if (lane == 0) sbuf[0] = tt;
        }
        __syncthreads();
    }
    float mu = sbuf[0] * (1.f / DM_);
    __syncthreads();

    float s2 = 0.f;
#pragma unroll
    for (int i = 0; i < 4; i++) { float d = v[i] - mu; s2 += d * d; }
    {
        int lane = tid & 31, wid = tid >> 5;
        for (int o = 16; o > 0; o >>= 1) s2 += __shfl_down_sync(0xffffffffu, s2, o);
        if (lane == 0) sbuf[wid] = s2;
        __syncthreads();
        if (wid == 0) {
            float tt = (lane < 8) ? sbuf[lane] : 0.f;
            for (int o = 4; o > 0; o >>= 1) tt += __shfl_down_sync(0xffffffffu, tt, o);
            if (lane == 0) sbuf[0] = tt;
        }
        __syncthreads();
    }
    float inv = rsqrtf(sbuf[0] * (1.f / DM_) + EPS_);

#pragma unroll
    for (int i = 0; i < 4; i++) {
        int c = tid + i * 256;
        out[(size_t)row * DM_ + c] = (v[i] - mu) * inv * gamma[c] + beta[c];
    }
}

// =================================================================================
// Launch: proj (parallel) -> stats -> fused pv+attn -> fc -> ln.
// =================================================================================
extern "C" void kernel_launch(void* const* d_in, const int* in_sizes, int n_in,
                              void* d_out, int out_size) {
    const float* q     = (const float*)d_in[0];
    const float* k     = (const float*)d_in[1];
    const float* v     = (const float*)d_in[2];
    const float* w_q   = (const float*)d_in[3];
    const float* w_k   = (const float*)d_in[4];
    const float* w_v   = (const float*)d_in[5];
    const float* w_fc  = (const float*)d_in[6];
    const float* gamma = (const float*)d_in[7];
    const float* beta  = (const float*)d_in[8];

    float* out  = (float*)d_out;
    float* attn = out + OUT_ELEMS;

    void *pQH, *pKH, *pVH, *pAO, *pFC, *pM, *pL;
    cudaGetSymbolAddress(&pQH, g_QH);
    cudaGetSymbolAddress(&pKH, g_KH);
    cudaGetSymbolAddress(&pVH, g_VH);
    cudaGetSymbolAddress(&pAO, g_AO);
    cudaGetSymbolAddress(&pFC, g_FC);
    cudaGetSymbolAddress(&pM, g_M);
    cudaGetSymbolAddress(&pL, g_L);
    float* QH = (float*)pQH; float* KH = (float*)pKH; float* VH = (float*)pVH;
    float* AO = (float*)pAO; float* FC = (float*)pFC;
    float* Mv = (float*)pM;  float* Lv = (float*)pL;

    static cudaStream_t s2 = nullptr, s3 = nullptr;
    static cudaEvent_t ev0 = nullptr, ev2, ev3;
    static bool attrs_set = false;
    if (!s2) {
        cudaStreamCreateWithFlags(&s2, cudaStreamNonBlocking);
        cudaStreamCreateWithFlags(&s3, cudaStreamNonBlocking);
        cudaEventCreateWithFlags(&ev0, cudaEventDisableTiming);
        cudaEventCreateWithFlags(&ev2, cudaEventDisableTiming);
        cudaEventCreateWithFlags(&ev3, cudaEventDisableTiming);
    }
    if (!attrs_set) {
        cudaFuncSetAttribute(gemm_tf32_kernel, cudaFuncAttributeMaxDynamicSharedMemorySize, GEMM_SMEM_BYTES);
        cudaFuncSetAttribute(attn_stats_kernel, cudaFuncAttributeMaxDynamicSharedMemorySize, ST_SMEM_BYTES);
        cudaFuncSetAttribute(attn_pv_kernel, cudaFuncAttributeMaxDynamicSharedMemorySize, PV_SMEM_BYTES);
        attrs_set = true;
    }

    dim3 gemm_grid(DM_ / 128, M8_ / 128);   // (8, 64)

    // fork: projections in parallel (fragment-major outputs; Q pre-scaled by 1/8)
    cudaEventRecord(ev0, 0);
    cudaStreamWaitEvent(s2, ev0, 0);
    cudaStreamWaitEvent(s3, ev0, 0);
    gemm_tf32_kernel<<<gemm_grid, 256, GEMM_SMEM_BYTES, 0>>>(q, w_q, QH, DM_, 1, nullptr, SCALE_);
    gemm_tf32_kernel<<<gemm_grid, 256, GEMM_SMEM_BYTES, s2>>>(k, w_k, KH, DM_, 2, nullptr, 1.0f);
    gemm_tf32_kernel<<<gemm_grid, 256, GEMM_SMEM_BYTES, s3>>>(v, w_v, VH, DM_, 3, nullptr, 1.0f);
    cudaEventRecord(ev2, s2);
    cudaEventRecord(ev3, s3);
    cudaStreamWaitEvent(0, ev2, 0);
    cudaStreamWaitEvent(0, ev3, 0);

    // pass 1: softmax stats (Mv, Lv)
    attn_stats_kernel<<<dim3(S_ / 128, BH_), 256, ST_SMEM_BYTES, 0>>>(QH, KH, Mv, Lv);

    // pass 2: fused PV + attn write
    attn_pv_kernel<<<dim3(S_ / 128, BH_), 256, PV_SMEM_BYTES, 0>>>(QH, KH, VH, Mv, Lv, AO, attn);

    // fc + residual, then layernorm
    gemm_tf32_kernel<<<gemm_grid, 256, GEMM_SMEM_BYTES, 0>>>(AO, w_fc, FC, DM_, 0, q, 1.0f);
    ln_kernel<<<M8_, 256, 0, 0>>>(FC, gamma, beta, out);
}

// round 16
// speedup vs baseline: 1.0791x; 1.0791x over previous
#include <cuda_runtime.h>
#include <cuda_bf16.h>
#include <math.h>
#include <stdint.h>

// Problem constants
#define B_ 4
#define S_ 2048
#define H_ 16
#define D_ 64
#define DM_ 1024
#define M8_ 8192
#define BH_ 64
#define SCALE_ 0.125f
#define EPS_ 1e-6f

#define OUT_ELEMS   (M8_ * DM_)
#define ATTN_ELEMS  ((size_t)BH_ * S_ * S_)

// ---------------- device scratch -----------------------------------------------
// QH/KH/VH hold tf32-ROUNDED values in FRAGMENT-MAJOR tile layouts:
//  QHf: per (bh, qtile=128 rows): [rg][kk][lane] uint4
//  KHf: per (bh, ktile=64 keys):  [kk][nt][lane] uint2
//  VHf: per (bh, ktile=64 keys):  [kc][nt][lane] uint2
// QHf additionally pre-scaled by 1/8.
__device__ float g_QH[(size_t)BH_ * S_ * D_];
__device__ float g_KH[(size_t)BH_ * S_ * D_];
__device__ float g_VH[(size_t)BH_ * S_ * D_];
__device__ float g_AO[(size_t)M8_ * DM_];       // [B,S,H*D] fp32
__device__ float g_FC[(size_t)M8_ * DM_];
__device__ float g_M[(size_t)BH_ * S_];
__device__ float g_L[(size_t)BH_ * S_];

// ---------------- tf32 helpers ---------------------------------------------------
__device__ __forceinline__ uint32_t f2tf32(float x) {
    uint32_t u;
    asm("cvt.rna.tf32.f32 %0, %1;" : "=r"(u) : "f"(x));
    return u;
}

__device__ __forceinline__ void mma8(float* c, const uint32_t* a, const uint32_t* b) {
    asm volatile(
        "mma.sync.aligned.m16n8k8.row.col.f32.tf32.tf32.f32 "
        "{%0,%1,%2,%3}, {%4,%5,%6,%7}, {%8,%9}, {%0,%1,%2,%3};"
        : "+f"(c[0]), "+f"(c[1]), "+f"(c[2]), "+f"(c[3])
        : "r"(a[0]), "r"(a[1]), "r"(a[2]), "r"(a[3]), "r"(b[0]), "r"(b[1]));
}

__device__ __forceinline__ void cp16(uint32_t saddr, const void* g) {
    asm volatile("cp.async.cg.shared.global [%0], [%1], 16;" :: "r"(saddr), "l"(g));
}
__device__ __forceinline__ void cp_commit() {
    asm volatile("cp.async.commit_group;");
}
// streaming (evict-first) 8-byte store: attn is write-once, never read.
__device__ __forceinline__ void stcs64(float* p, float2 v) {
    asm volatile("st.global.cs.v2.f32 [%0], {%1, %2};" :: "l"(p), "f"(v.x), "f"(v.y) : "memory");
}

// =================================================================================
// tf32 GEMM: hm 0=row-major fc; 1=Q-frag; 2=K-frag; 3=V-frag.
// =================================================================================
#define GEMM_SMEM_BYTES (4 * 128 * 36 * 4)

__global__ __launch_bounds__(256) void gemm_tf32_kernel(
    const float* __restrict__ A, const float* __restrict__ W, float* __restrict__ C,
    int K, int hm, const float* __restrict__ resid, float oscale) {
    extern __shared__ uint32_t dynsm[];
    uint32_t* As = dynsm;
    uint32_t* Ws = dynsm + 2 * 4608;

    const int tid = threadIdx.x;
    const int lane = tid & 31, warp = tid >> 5;
    const int wm = warp >> 1, wn = warp & 1;
    const int rm = wm * 32, cn = wn * 64;
    const int m0 = blockIdx.y * 128, n0 = blockIdx.x * 128;

    const int lr0 = tid >> 3, lr1 = (tid + 256) >> 3, lr2 = (tid + 512) >> 3, lr3 = (tid + 768) >> 3;
    const int lc = (tid & 7) * 4;

    float acc[2][8][4];
#pragma unroll
    for (int mt = 0; mt < 2; mt++)
#pragma unroll
        for (int nt = 0; nt < 8; nt++)
#pragma unroll
            for (int i = 0; i < 4; i++) acc[mt][nt][i] = 0.f;

    const int NT = K >> 5;

    float4 pa0, pa1, pa2, pa3, pw0, pw1, pw2, pw3;
    pa0 = *(const float4*)(A + (size_t)(m0 + lr0) * K + lc);
    pa1 = *(const float4*)(A + (size_t)(m0 + lr1) * K + lc);
    pa2 = *(const float4*)(A + (size_t)(m0 + lr2) * K + lc);
    pa3 = *(const float4*)(A + (size_t)(m0 + lr3) * K + lc);
    pw0 = *(const float4*)(W + (size_t)(n0 + lr0) * K + lc);
    pw1 = *(const float4*)(W + (size_t)(n0 + lr1) * K + lc);
    pw2 = *(const float4*)(W + (size_t)(n0 + lr2) * K + lc);
    pw3 = *(const float4*)(W + (size_t)(n0 + lr3) * K + lc);

#define STORE_TILE(buf)                                                                    \
    do {                                                                                   \
        uint32_t* Ab_ = As + (buf) * 4608;                                                 \
        uint32_t* Wb_ = Ws + (buf) * 4608;                                                 \
        *(uint4*)&Ab_[lr0 * 36 + lc] = make_uint4(f2tf32(pa0.x), f2tf32(pa0.y), f2tf32(pa0.z), f2tf32(pa0.w)); \
        *(uint4*)&Ab_[lr1 * 36 + lc] = make_uint4(f2tf32(pa1.x), f2tf32(pa1.y), f2tf32(pa1.z), f2tf32(pa1.w)); \
        *(uint4*)&Ab_[lr2 * 36 + lc] = make_uint4(f2tf32(pa2.x), f2tf32(pa2.y), f2tf32(pa2.z), f2tf32(pa2.w)); \
        *(uint4*)&Ab_[lr3 * 36 + lc] = make_uint4(f2tf32(pa3.x), f2tf32(pa3.y), f2tf32(pa3.z), f2tf32(pa3.w)); \
        *(uint4*)&Wb_[lr0 * 36 + lc] = make_uint4(f2tf32(pw0.x), f2tf32(pw0.y), f2tf32(pw0.z), f2tf32(pw0.w)); \
        *(uint4*)&Wb_[lr1 * 36 + lc] = make_uint4(f2tf32(pw1.x), f2tf32(pw1.y), f2tf32(pw1.z), f2tf32(pw1.w)); \
        *(uint4*)&Wb_[lr2 * 36 + lc] = make_uint4(f2tf32(pw2.x), f2tf32(pw2.y), f2tf32(pw2.z), f2tf32(pw2.w)); \
        *(uint4*)&Wb_[lr3 * 36 + lc] = make_uint4(f2tf32(pw3.x), f2tf32(pw3.y), f2tf32(pw3.z), f2tf32(pw3.w)); \
    } while (0)

    STORE_TILE(0);

    for (int kt = 0; kt < NT; kt++) {
        __syncthreads();
        if (kt + 1 < NT) {
            const int ko = (kt + 1) * 32;
            pa0 = *(const float4*)(A + (size_t)(m0 + lr0) * K + ko + lc);
            pa1 = *(const float4*)(A + (size_t)(m0 + lr1) * K + ko + lc);
            pa2 = *(const float4*)(A + (size_t)(m0 + lr2) * K + ko + lc);
            pa3 = *(const float4*)(A + (size_t)(m0 + lr3) * K + ko + lc);
            pw0 = *(const float4*)(W + (size_t)(n0 + lr0) * K + ko + lc);
            pw1 = *(const float4*)(W + (size_t)(n0 + lr1) * K + ko + lc);
            pw2 = *(const float4*)(W + (size_t)(n0 + lr2) * K + ko + lc);
            pw3 = *(const float4*)(W + (size_t)(n0 + lr3) * K + ko + lc);
        }

        const uint32_t* Ab = As + (kt & 1) * 4608;
        const uint32_t* Wb = Ws + (kt & 1) * 4608;
#pragma unroll
        for (int kk = 0; kk < 4; kk++) {
            const int c0 = kk * 8 + (lane & 3);
            uint32_t a[2][4];
#pragma unroll
            for (int mt = 0; mt < 2; mt++) {
                int r0 = rm + mt * 16 + (lane >> 2);
                a[mt][0] = Ab[r0 * 36 + c0];
                a[mt][1] = Ab[(r0 + 8) * 36 + c0];
                a[mt][2] = Ab[r0 * 36 + c0 + 4];
                a[mt][3] = Ab[(r0 + 8) * 36 + c0 + 4];
            }
            uint32_t b[8][2];
#pragma unroll
            for (int nt = 0; nt < 8; nt++) {
                int rb = cn + nt * 8 + (lane >> 2);
                b[nt][0] = Wb[rb * 36 + c0];
                b[nt][1] = Wb[rb * 36 + c0 + 4];
            }
#pragma unroll
            for (int mt = 0; mt < 2; mt++)
#pragma unroll
                for (int nt = 0; nt < 8; nt++) mma8(acc[mt][nt], a[mt], b[nt]);
        }

        if (kt + 1 < NT) STORE_TILE((kt + 1) & 1);
    }

#pragma unroll
    for (int mt = 0; mt < 2; mt++) {
#pragma unroll
        for (int nt = 0; nt < 8; nt++) {
#pragma unroll
            for (int half = 0; half < 2; half++) {
                int row = m0 + rm + mt * 16 + (lane >> 2) + half * 8;
                int col = n0 + cn + nt * 8 + 2 * (lane & 3);
                float v0 = acc[mt][nt][half * 2 + 0];
                float v1 = acc[mt][nt][half * 2 + 1];
                if (resid) {
                    v0 += resid[(size_t)row * DM_ + col];
                    v1 += resid[(size_t)row * DM_ + col + 1];
                }
                if (hm == 0) {
                    *(float2*)&C[(size_t)row * DM_ + col] = make_float2(v0, v1);
                } else {
                    v0 = __uint_as_float(f2tf32(v0 * oscale));
                    v1 = __uint_as_float(f2tf32(v1 * oscale));
                    int b = row >> 11, s = row & (S_ - 1);
                    int h = col >> 6, d = col & (D_ - 1);
                    int bh = b * H_ + h;
                    if (hm == 1) {
                        int qt = s >> 7, r = s & 127, rg = r >> 4, rr = r & 15;
                        int g8 = rr & 7, hi = rr >> 3;
                        size_t base = ((size_t)bh * 16 + qt) * 8192;
                        int kk = d >> 3, cc = d & 7, t = cc & 3, w = cc >> 2;
                        C[base + (size_t)(((rg * 8 + kk) * 32 + (g8 * 4 + t)) * 4 + hi + 2 * w)] = v0;
                        int d1 = d + 1; kk = d1 >> 3; cc = d1 & 7; t = cc & 3; w = cc >> 2;
                        C[base + (size_t)(((rg * 8 + kk) * 32 + (g8 * 4 + t)) * 4 + hi + 2 * w)] = v1;
                    } else if (hm == 2) {
                        int kt = s >> 6, r = s & 63, nt2 = r >> 3, g8 = r & 7;
                        size_t base = ((size_t)bh * 32 + kt) * 4096;
                        int kk = d >> 3, cc = d & 7, t = cc & 3, w = cc >> 2;
                        C[base + (size_t)(((kk * 8 + nt2) * 32 + (g8 * 4 + t)) * 2 + w)] = v0;
                        int d1 = d + 1; kk = d1 >> 3; cc = d1 & 7; t = cc & 3; w = cc >> 2;
                        C[base + (size_t)(((kk * 8 + nt2) * 32 + (g8 * 4 + t)) * 2 + w)] = v1;
                    } else {
                        int kt = s >> 6, rk = s & 63, kc = rk >> 3, u = rk & 7;
                        int t = u & 3, w = u >> 2;
                        size_t base = ((size_t)bh * 32 + kt) * 4096;
                        int nt2 = d >> 3, g8 = d & 7;
                        C[base + (size_t)(((kc * 8 + nt2) * 32 + (g8 * 4 + t)) * 2 + w)] = v0;
                        int d1 = d + 1; nt2 = d1 >> 3; g8 = d1 & 7;
                        C[base + (size_t)(((kc * 8 + nt2) * 32 + (g8 * 4 + t)) * 2 + w)] = v1;
                    }
                }
            }
        }
    }
#undef STORE_TILE
}

// =================================================================================
// Attention pass A (R13): fragment-major inputs, contiguous cp.async, flash with
// register online softmax. smem 24576 words (96 KB), 2 CTAs/SM.
// =================================================================================
#define AA_SMEM_BYTES (24576 * 4)

__global__ __launch_bounds__(256, 2) void attn_a_tf32_kernel(
    const float* __restrict__ QHf, const float* __restrict__ KHf,
    const float* __restrict__ VHf, float* __restrict__ AO,
    float* __restrict__ Mv, float* __restrict__ Lv) {
    extern __shared__ uint32_t sm[];
    const uint32_t sbase = (uint32_t)__cvta_generic_to_shared(sm);

    const int tid = threadIdx.x;
    const int lane = tid & 31, warp = tid >> 5;
    const int g = lane >> 2, t = lane & 3;
    const int r0 = warp * 16 + g;
    const int bh = blockIdx.y;
    const int q0 = blockIdx.x * 128;
    const int srcA = (lane & ~3) | (t >> 1);
    const int srcB = srcA + 2;

    const float* Qt = QHf + ((size_t)bh * 16 + blockIdx.x) * 8192;
    const float* Kt = KHf + (size_t)bh * 32 * 4096;
    const float* Vt = VHf + (size_t)bh * 32 * 4096;

    const int NT = S_ / 64;

#define ISSUE_KV(stage, kt_)                                                          \
    do {                                                                              \
        const float* Kg_ = Kt + (size_t)(kt_) * 4096;                                 \
        const float* Vg_ = Vt + (size_t)(kt_) * 4096;                                 \
        _Pragma("unroll")                                                             \
        for (int p = 0; p < 4; p++) {                                                 \
            int w4 = (tid + p * 256) * 4;                                             \
            cp16(sbase + (uint32_t)(8192 + (stage) * 4096 + w4) * 4, Kg_ + w4);       \
            cp16(sbase + (uint32_t)(16384 + (stage) * 4096 + w4) * 4, Vg_ + w4);      \
        }                                                                             \
        cp_commit();                                                                  \
    } while (0)

#pragma unroll
    for (int p = 0; p < 8; p++) {
        int w4 = (tid + p * 256) * 4;
        cp16(sbase + (uint32_t)w4 * 4, Qt + w4);
    }
#pragma unroll
    for (int p = 0; p < 4; p++) {
        int w4 = (tid + p * 256) * 4;
        cp16(sbase + (uint32_t)(8192 + w4) * 4, Kt + w4);
        cp16(sbase + (uint32_t)(16384 + w4) * 4, Vt + w4);
    }
    cp_commit();
    ISSUE_KV(1, 1);

    float o[8][4];
#pragma unroll
    for (int nt = 0; nt < 8; nt++)
#pragma unroll
        for (int i = 0; i < 4; i++) o[nt][i] = 0.f;

    float rowm0 = -1e30f, rowm1 = -1e30f;
    float rowl0 = 0.f, rowl1 = 0.f;

    for (int kt = 0; kt < NT; kt++) {
        if (kt + 1 < NT) asm volatile("cp.async.wait_group 1;");
        else             asm volatile("cp.async.wait_group 0;");
        __syncthreads();

        const uint32_t* Kb = sm + 8192 + (kt & 1) * 4096;
        const uint32_t* Vb = sm + 16384 + (kt & 1) * 4096;

        float sacc[8][4];
#pragma unroll
        for (int nt = 0; nt < 8; nt++)
#pragma unroll
            for (int i = 0; i < 4; i++) sacc[nt][i] = 0.f;

#pragma unroll
        for (int kk = 0; kk < 8; kk++) {
            uint4 av = *(const uint4*)&sm[(((warp << 3) + kk) * 32 + lane) * 4];
            uint32_t a[4] = {av.x, av.y, av.z, av.w};
#pragma unroll
            for (int nt = 0; nt < 8; nt++) {
                uint2 bv = *(const uint2*)&Kb[((kk * 8 + nt) * 32 + lane) * 2];
                uint32_t b[2] = {bv.x, bv.y};
                mma8(sacc[nt], a, b);
            }
        }

        float mx0 = -1e30f, mx1 = -1e30f;
#pragma unroll
        for (int nt = 0; nt < 8; nt++) {
            mx0 = fmaxf(mx0, fmaxf(sacc[nt][0], sacc[nt][1]));
            mx1 = fmaxf(mx1, fmaxf(sacc[nt][2], sacc[nt][3]));
        }
        mx0 = fmaxf(mx0, __shfl_xor_sync(0xffffffffu, mx0, 1));
        mx0 = fmaxf(mx0, __shfl_xor_sync(0xffffffffu, mx0, 2));
        mx1 = fmaxf(mx1, __shfl_xor_sync(0xffffffffu, mx1, 1));
        mx1 = fmaxf(mx1, __shfl_xor_sync(0xffffffffu, mx1, 2));

        float mn0 = fmaxf(rowm0, mx0), mn1 = fmaxf(rowm1, mx1);
        float cr0 = __expf(rowm0 - mn0), cr1 = __expf(rowm1 - mn1);
        float ps0 = 0.f, ps1 = 0.f;
#pragma unroll
        for (int nt = 0; nt < 8; nt++) {
            sacc[nt][0] = __expf(sacc[nt][0] - mn0); ps0 += sacc[nt][0];
            sacc[nt][1] = __expf(sacc[nt][1] - mn0); ps0 += sacc[nt][1];
            sacc[nt][2] = __expf(sacc[nt][2] - mn1); ps1 += sacc[nt][2];
            sacc[nt][3] = __expf(sacc[nt][3] - mn1); ps1 += sacc[nt][3];
        }
        ps0 += __shfl_xor_sync(0xffffffffu, ps0, 1);
        ps0 += __shfl_xor_sync(0xffffffffu, ps0, 2);
        ps1 += __shfl_xor_sync(0xffffffffu, ps1, 1);
        ps1 += __shfl_xor_sync(0xffffffffu, ps1, 2);
        rowl0 = rowl0 * cr0 + ps0; rowm0 = mn0;
        rowl1 = rowl1 * cr1 + ps1; rowm1 = mn1;

#pragma unroll
        for (int nt = 0; nt < 8; nt++) {
            o[nt][0] *= cr0; o[nt][1] *= cr0;
            o[nt][2] *= cr1; o[nt][3] *= cr1;
        }

#pragma unroll
        for (int kc = 0; kc < 8; kc++) {
            uint32_t p0 = f2tf32(sacc[kc][0]);
            uint32_t p1 = f2tf32(sacc[kc][1]);
            uint32_t p2 = f2tf32(sacc[kc][2]);
            uint32_t p3 = f2tf32(sacc[kc][3]);
            uint32_t pa[4];
            {
                uint32_t u0 = __shfl_sync(0xffffffffu, p0, srcA);
                uint32_t u1 = __shfl_sync(0xffffffffu, p1, srcA);
                pa[0] = (lane & 1) ? u1 : u0;
                u0 = __shfl_sync(0xffffffffu, p2, srcA);
                u1 = __shfl_sync(0xffffffffu, p3, srcA);
                pa[1] = (lane & 1) ? u1 : u0;
                u0 = __shfl_sync(0xffffffffu, p0, srcB);
                u1 = __shfl_sync(0xffffffffu, p1, srcB);
                pa[2] = (lane & 1) ? u1 : u0;
                u0 = __shfl_sync(0xffffffffu, p2, srcB);
                u1 = __shfl_sync(0xffffffffu, p3, srcB);
                pa[3] = (lane & 1) ? u1 : u0;
            }
#pragma unroll
            for (int nt = 0; nt < 8; nt++) {
                uint2 bv = *(const uint2*)&Vb[((kc * 8 + nt) * 32 + lane) * 2];
                uint32_t b[2] = {bv.x, bv.y};
                mma8(o[nt], pa, b);
            }
        }

        __syncthreads();
        if (kt + 2 < NT) ISSUE_KV(kt & 1, kt + 2);
    }
#undef ISSUE_KV

    const int bb = bh >> 4, hh = bh & 15;
    float il0 = 1.f / rowl0, il1 = 1.f / rowl1;
#pragma unroll
    for (int nt = 0; nt < 8; nt++) {
        int col = hh * D_ + nt * 8 + 2 * t;
        size_t base0 = ((size_t)bb * S_ + (q0 + r0)) * DM_ + col;
        size_t base1 = ((size_t)bb * S_ + (q0 + r0 + 8)) * DM_ + col;
        *(float2*)&AO[base0] = make_float2(o[nt][0] * il0, o[nt][1] * il0);
        *(float2*)&AO[base1] = make_float2(o[nt][2] * il1, o[nt][3] * il1);
    }
    if (t == 0) {
        size_t mb = (size_t)bh * S_ + q0 + r0;
        Mv[mb] = rowm0;     Lv[mb] = rowl0;
        Mv[mb + 8] = rowm1; Lv[mb + 8] = rowl1;
    }
}

// =================================================================================
// Attention pass B (R13 + streaming stores): fragment-major Q/K; 128 q x 512 k,
// K double-buffered; attn written with st.global.cs (evict-first).
// =================================================================================
#define AB_SMEM_BYTES (24832 * 4)

__global__ __launch_bounds__(256, 2) void attn_b_tf32_kernel(
    const float* __restrict__ QHf, const float* __restrict__ KHf,
    const float* __restrict__ Mv, const float* __restrict__ Lv,
    float* __restrict__ attn) {
    extern __shared__ uint32_t sm[];
    const uint32_t sbase = (uint32_t)__cvta_generic_to_shared(sm);
    float* fm = (float*)(sm + 24576);
    float* fl = fm + 128;

    const int tid = threadIdx.x;
    const int lane = tid & 31, warp = tid >> 5;
    const int wm = warp >> 1, wn = warp & 1;
    const int rm = wm * 32, cn = wn * 64;
    const int bh = blockIdx.z;
    const int q0 = blockIdx.y * 128;
    const int kbase = blockIdx.x * 512;

    const float* Qt = QHf + ((size_t)bh * 16 + blockIdx.y) * 8192;
    const float* Kt = KHf + (size_t)bh * 32 * 4096;

#define ISSUE_K(stage, kt64_)                                                         \
    do {                                                                              \
        const float* Kg_ = Kt + (size_t)(kt64_) * 4096;                               \
        _Pragma("unroll")                                                             \
        for (int p = 0; p < 8; p++) {                                                 \
            int w4 = (tid + p * 256) * 4;                                             \
            cp16(sbase + (uint32_t)(8192 + (stage) * 8192 + w4) * 4, Kg_ + w4);       \
        }                                                                             \
        cp_commit();                                                                  \
    } while (0)

#pragma unroll
    for (int p = 0; p < 8; p++) {
        int w4 = (tid + p * 256) * 4;
        cp16(sbase + (uint32_t)w4 * 4, Qt + w4);
        cp16(sbase + (uint32_t)(8192 + w4) * 4, Kt + (size_t)(kbase >> 6) * 4096 + w4);
    }
    cp_commit();
    ISSUE_K(1, (kbase >> 6) + 2);

    if (tid < 128) {
        fm[tid] = Mv[(size_t)bh * S_ + q0 + tid];
        fl[tid] = 1.f / Lv[(size_t)bh * S_ + q0 + tid];
    }

    for (int kt = 0; kt < 4; kt++) {
        if (kt + 1 < 4) asm volatile("cp.async.wait_group 1;");
        else            asm volatile("cp.async.wait_group 0;");
        __syncthreads();

        const uint32_t* Ks = sm + 8192 + (kt & 1) * 8192 + wn * 4096;
        const int k0 = kbase + kt * 128;

        float acc[2][8][4];
#pragma unroll
        for (int mt = 0; mt < 2; mt++)
#pragma unroll
            for (int nt = 0; nt < 8; nt++)
#pragma unroll
                for (int i = 0; i < 4; i++) acc[mt][nt][i] = 0.f;

#pragma unroll
        for (int kk = 0; kk < 8; kk++) {
            uint32_t a[2][4];
#pragma unroll
            for (int mt = 0; mt < 2; mt++) {
                int rg = wm * 2 + mt;
                uint4 av = *(const uint4*)&sm[((rg * 8 + kk) * 32 + lane) * 4];
                a[mt][0] = av.x; a[mt][1] = av.y; a[mt][2] = av.z; a[mt][3] = av.w;
            }
#pragma unroll
            for (int nt = 0; nt < 8; nt++) {
                uint2 bv = *(const uint2*)&Ks[((kk * 8 + nt) * 32 + lane) * 2];
                uint32_t b[2] = {bv.x, bv.y};
#pragma unroll
                for (int mt = 0; mt < 2; mt++) mma8(acc[mt][nt], a[mt], b);
            }
        }

#pragma unroll
        for (int mt = 0; mt < 2; mt++) {
#pragma unroll
            for (int half = 0; half < 2; half++) {
                int r0 = rm + mt * 16 + (lane >> 2) + half * 8;
                float m = fm[r0], il = fl[r0];
                size_t rowbase = ((size_t)bh * S_ + (q0 + r0)) * S_ + k0;
#pragma unroll
                for (int nt = 0; nt < 8; nt++) {
                    int c = cn + nt * 8 + 2 * (lane & 3);
                    float2 v;
                    v.x = __expf(acc[mt][nt][half * 2 + 0] - m) * il;
                    v.y = __expf(acc[mt][nt][half * 2 + 1] - m) * il;
                    stcs64(&attn[rowbase + c], v);
                }
            }
        }

        __syncthreads();
        if (kt + 2 < 4) ISSUE_K(kt & 1, (kbase >> 6) + (kt + 2) * 2);
    }
#undef ISSUE_K
}

// =================================================================================
// LayerNorm over last dim (1024).
// =================================================================================
__global__ void ln_kernel(const float* __restrict__ FC, const float* __restrict__ gamma,
                          const float* __restrict__ beta, float* __restrict__ out) {
    __shared__ float sbuf[32];
    const int row = blockIdx.x;
    const int tid = threadIdx.x;
    const float* x = FC + (size_t)row * DM_;

    float v[4];
    float s = 0.f;
#pragma unroll
    for (int i = 0; i < 4; i++) { v[i] = x[tid + i * 256]; s += v[i]; }
    {
        int lane = tid & 31, wid = tid >> 5;
        for (int o = 16; o > 0; o >>= 1) s += __shfl_down_sync(0xffffffffu, s, o);
        if (lane == 0) sbuf[wid] = s;
        __syncthreads();
        if (wid == 0) {
            float tt = (lane < 8) ? sbuf[lane] : 0.f;
            for (int o = 4; o > 0; o >>= 1) tt += __shfl_down_sync(0xffffffffu, tt, o);
            if (lane == 0) sbuf[0] = tt;
        }
        __syncthreads();
    }
    float mu = sbuf[0] * (1.f / DM_);
    __syncthreads();

    float s2 = 0.f;
#pragma unroll
    for (int i = 0; i < 4; i++) { float d = v[i] - mu; s2 += d * d; }
    {
        int lane = tid & 31, wid = tid >> 5;
        for (int o = 16; o > 0; o >>= 1) s2 += __shfl_down_sync(0xffffffffu, s2, o);
        if (lane == 0) sbuf[wid] = s2;
        __syncthreads();
        if (wid == 0) {
            float tt = (lane < 8) ? sbuf[lane] : 0.f;
            for (int o = 4; o > 0; o >>= 1) tt += __shfl_down_sync(0xffffffffu, tt, o);
            if (lane == 0) sbuf[0] = tt;
        }
        __syncthreads();
    }
    float inv = rsqrtf(sbuf[0] * (1.f / DM_) + EPS_);

#pragma unroll
    for (int i = 0; i < 4; i++) {
        int c = tid + i * 256;
        out[(size_t)row * DM_ + c] = (v[i] - mu) * inv * gamma[c] + beta[c];
    }
}

// =================================================================================
// Launch — R13 schedule: proj∥ -> attn_a -> attn_b ∥ (fc + ln).
// =================================================================================
extern "C" void kernel_launch(void* const* d_in, const int* in_sizes, int n_in,
                              void* d_out, int out_size) {
    const float* q     = (const float*)d_in[0];
    const float* k     = (const float*)d_in[1];
    const float* v     = (const float*)d_in[2];
    const float* w_q   = (const float*)d_in[3];
    const float* w_k   = (const float*)d_in[4];
    const float* w_v   = (const float*)d_in[5];
    const float* w_fc  = (const float*)d_in[6];
    const float* gamma = (const float*)d_in[7];
    const float* beta  = (const float*)d_in[8];

    float* out  = (float*)d_out;
    float* attn = out + OUT_ELEMS;

    void *pQH, *pKH, *pVH, *pAO, *pFC, *pM, *pL;
    cudaGetSymbolAddress(&pQH, g_QH);
    cudaGetSymbolAddress(&pKH, g_KH);
    cudaGetSymbolAddress(&pVH, g_VH);
    cudaGetSymbolAddress(&pAO, g_AO);
    cudaGetSymbolAddress(&pFC, g_FC);
    cudaGetSymbolAddress(&pM, g_M);
    cudaGetSymbolAddress(&pL, g_L);
    float* QH = (float*)pQH; float* KH = (float*)pKH; float* VH = (float*)pVH;
    float* AO = (float*)pAO; float* FC = (float*)pFC;
    float* Mv = (float*)pM;  float* Lv = (float*)pL;

    static cudaStream_t s2 = nullptr, s3 = nullptr;
    static cudaEvent_t ev0 = nullptr, ev2, ev3, evA, evB;
    static bool attrs_set = false;
    if (!s2) {
        cudaStreamCreateWithFlags(&s2, cudaStreamNonBlocking);
        cudaStreamCreateWithFlags(&s3, cudaStreamNonBlocking);
        cudaEventCreateWithFlags(&ev0, cudaEventDisableTiming);
        cudaEventCreateWithFlags(&ev2, cudaEventDisableTiming);
        cudaEventCreateWithFlags(&ev3, cudaEventDisableTiming);
        cudaEventCreateWithFlags(&evA, cudaEventDisableTiming);
        cudaEventCreateWithFlags(&evB, cudaEventDisableTiming);
    }
    if (!attrs_set) {
        cudaFuncSetAttribute(gemm_tf32_kernel, cudaFuncAttributeMaxDynamicSharedMemorySize, GEMM_SMEM_BYTES);
        cudaFuncSetAttribute(attn_a_tf32_kernel, cudaFuncAttributeMaxDynamicSharedMemorySize, AA_SMEM_BYTES);
        cudaFuncSetAttribute(attn_b_tf32_kernel, cudaFuncAttributeMaxDynamicSharedMemorySize, AB_SMEM_BYTES);
        attrs_set = true;
    }

    dim3 gemm_grid(DM_ / 128, M8_ / 128);   // (8, 64)
    const bool want_attn = (size_t)out_size >= OUT_ELEMS + ATTN_ELEMS;

    // fork: projections in parallel (fragment-major outputs; Q pre-scaled by 1/8)
    cudaEventRecord(ev0, 0);
    cudaStreamWaitEvent(s2, ev0, 0);
    cudaStreamWaitEvent(s3, ev0, 0);
    gemm_tf32_kernel<<<gemm_grid, 256, GEMM_SMEM_BYTES, 0>>>(q, w_q, QH, DM_, 1, nullptr, SCALE_);
    gemm_tf32_kernel<<<gemm_grid, 256, GEMM_SMEM_BYTES, s2>>>(k, w_k, KH, DM_, 2, nullptr, 1.0f);
    gemm_tf32_kernel<<<gemm_grid, 256, GEMM_SMEM_BYTES, s3>>>(v, w_v, VH, DM_, 3, nullptr, 1.0f);
    cudaEventRecord(ev2, s2);
    cudaEventRecord(ev3, s3);
    cudaStreamWaitEvent(0, ev2, 0);
    cudaStreamWaitEvent(0, ev3, 0);

    // pass A: flash attention -> AO + (m, l)
    attn_a_tf32_kernel<<<dim3(S_ / 128, BH_), 256, AA_SMEM_BYTES, 0>>>(QH, KH, VH, AO, Mv, Lv);

    // fork: attn_b concurrent with fc+ln
    cudaEventRecord(evA, 0);
    if (want_attn) {
        cudaStreamWaitEvent(s2, evA, 0);
        attn_b_tf32_kernel<<<dim3(S_ / 512, S_ / 128, BH_), 256, AB_SMEM_BYTES, s2>>>(QH, KH, Mv, Lv, attn);
        cudaEventRecord(evB, s2);
    }

    gemm_tf32_kernel<<<gemm_grid, 256, GEMM_SMEM_BYTES, 0>>>(AO, w_fc, FC, DM_, 0, q, 1.0f);
    ln_kernel<<<M8_, 256, 0, 0>>>(FC, gamma, beta, out);

    if (want_attn) {
        cudaStreamWaitEvent(0, evB, 0);   // join before returning to harness
    }
}